// round 14
// baseline (speedup 1.0000x reference)
#include <cuda_runtime.h>
#include <cstdint>

#define NQ 4096
#define TPB 256

// Swizzle: s(e) = e ^ ((e>>5 & 7)<<2) ^ ((e>>8 & 1)<<4).
// Bank bits of s(e): {e0, e1, e2^e5, e3^e6, e4^e7^e8}.
// Bijective on [0,4096); XORs only into bits 2-4 -> float4 alignment kept.
// Conflict-free for all three smem patterns below:
//   A (STS):  e = r*256 + t          -> lanes vary e0-4 directly
//   B (f4):   e = 16t + 4q           -> chunk bits {q0^t1, q1^t2, t0^t3}
//   C (LDS):  e = (t&15)|(i<<4)|((t>>4)<<8) -> {t0,t1,t2^i1,t3^i2,i0^i3^t4}
__device__ __forceinline__ int s_idx(int e) {
    return e ^ (((e >> 5) & 7) << 2) ^ (((e >> 8) & 1) << 4);
}

__device__ __forceinline__ void butterfly16(float v[16]) {
#pragma unroll
    for (int bs = 1; bs < 16; bs <<= 1) {
#pragma unroll
        for (int i = 0; i < 16; i++) {
            if ((i & bs) == 0) {
                float a = v[i], b = v[i + bs];
                v[i] = a + b;
                v[i + bs] = a - b;
            }
        }
    }
}

// 4096-pt FWHT, one row per CTA, 16 floats per thread.
//   P1: regs = dims {8-11}, loaded via the read-only path (16 coalesced
//       LDG.32.CONSTANT, one full 128B line per warp-instruction, 16-deep MLP)
//   P2: regs = dims {0-3}, via one smem exchange (float4, in-place)
//   P3: regs = dims {4-7}, stored directly to gmem (coalesced STG.32)
// One smem exchange pair + 2 barriers; every leg bank-conflict-free.
//
// Measured at the mixed read+write HBM ceiling (~5.9 TB/s effective, 74% of
// spec): seven structural variants (shuffle ladder, TMA swizzle, bulk
// prefetch, persistent pipeline, evict-first stores, ...) all wall-equal at
// 45.5us, so the chassis with the best occupancy (90%, 32 regs) and the
// fewest moving parts wins.
__global__ void __launch_bounds__(TPB, 8) fwht4096_kernel(const float* __restrict__ x,
                                                          float* __restrict__ y) {
    __shared__ float sm[NQ];  // 16 KB
    const int t = threadIdx.x;
    const size_t base = (size_t)blockIdx.x * NQ;
    const float scale = 0.015625f;  // HAD_SCALE / X_H_SCALE = 1/sqrt(4096)
    float v[16];

    // ---- P1: v[r] = x[r*256 + t] (read-only path) ----
    const float* xr = x + base + t;
#pragma unroll
    for (int r = 0; r < 16; r++)
        v[r] = __ldg(xr + r * 256) * scale;
    butterfly16(v);  // dims 8-11

    // Pattern A: conflict-free STS
#pragma unroll
    for (int r = 0; r < 16; r++)
        sm[s_idx(r * 256 + t)] = v[r];
    __syncthreads();

    // ---- P2: regs = dims 0-3 (pattern B, float4, in-place) ----
#pragma unroll
    for (int q = 0; q < 4; q++) {
        float4 f = *reinterpret_cast<const float4*>(sm + s_idx((t << 4) | (q << 2)));
        v[4 * q + 0] = f.x;
        v[4 * q + 1] = f.y;
        v[4 * q + 2] = f.z;
        v[4 * q + 3] = f.w;
    }
    butterfly16(v);  // dims 0-3
#pragma unroll
    for (int q = 0; q < 4; q++) {
        *reinterpret_cast<float4*>(sm + s_idx((t << 4) | (q << 2))) =
            make_float4(v[4 * q], v[4 * q + 1], v[4 * q + 2], v[4 * q + 3]);
    }
    __syncthreads();

    // ---- P3: regs = dims 4-7 (pattern C) ----
    const int ebase = (t & 15) | ((t >> 4) << 8);
#pragma unroll
    for (int i = 0; i < 16; i++)
        v[i] = sm[s_idx(ebase | (i << 4))];
    butterfly16(v);  // dims 4-7

    // ---- Store: 16 x STG.32; each instruction covers two full 64B segments ----
    float* yr = y + base;
#pragma unroll
    for (int i = 0; i < 16; i++)
        yr[ebase | (i << 4)] = v[i];
}

extern "C" void kernel_launch(void* const* d_in, const int* in_sizes, int n_in,
                              void* d_out, int out_size) {
    const float* x = (const float*)d_in[0];
    float* y = (float*)d_out;
    const int rows = in_sizes[0] / NQ;  // 8192 rows of 4096
    fwht4096_kernel<<<rows, TPB>>>(x, y);
}

// round 15
// speedup vs baseline: 1.0352x; 1.0352x over previous
#include <cuda_runtime.h>
#include <cstdint>

#define NQ 4096
#define TPB 256

// Swizzle: s(e) = e ^ ((e>>5 & 7)<<2) ^ ((e>>8 & 1)<<4).
// Bank bits of s(e): {e0, e1, e2^e5, e3^e6, e4^e7^e8}.
// Bijective on [0,4096); XORs only into bits 2-4 -> float4 alignment kept.
// Conflict-free for all three smem patterns below:
//   A (STS):  e = r*256 + t          -> lanes vary e0-4 directly
//   B (f4):   e = 16t + 4q           -> chunk bits {q0^t1, q1^t2, t0^t3}
//   C (LDS):  e = (t&15)|(i<<4)|((t>>4)<<8) -> {t0,t1,t2^i1,t3^i2,i0^i3^t4}
__device__ __forceinline__ int s_idx(int e) {
    return e ^ (((e >> 5) & 7) << 2) ^ (((e >> 8) & 1) << 4);
}

__device__ __forceinline__ void butterfly16(float v[16]) {
#pragma unroll
    for (int bs = 1; bs < 16; bs <<= 1) {
#pragma unroll
        for (int i = 0; i < 16; i++) {
            if ((i & bs) == 0) {
                float a = v[i], b = v[i + bs];
                v[i] = a + b;
                v[i + bs] = a - b;
            }
        }
    }
}

// 4096-pt FWHT, one row per CTA, 16 floats per thread.
//   P1: regs = dims {8-11}, loaded directly from gmem (16 coalesced LDG.32,
//       one full 128B line per warp-instruction, 16-deep MLP)
//   P2: regs = dims {0-3}, via one smem exchange (float4, in-place)
//   P3: regs = dims {4-7}, stored directly to gmem (coalesced STG.32)
// One smem exchange pair + 2 barriers; every leg bank-conflict-free.
//
// Final configuration. Measured 45.53-45.57us across three runs — the mixed
// read+write HBM ceiling (268MB / 45.5us = 5.9 TB/s effective, 74% of spec).
// Eight structural variants (shuffle ladder, TMA swizzle, bulk prefetch,
// persistent pipeline, evict-first stores, read-only path) were all wall-
// equal or worse; every SM-side pipe has >=35% headroom (L1 64%, L2 34%,
// issue 55%). This chassis wins on occupancy (90%, 32 regs) and simplicity.
__global__ void __launch_bounds__(TPB, 8) fwht4096_kernel(const float* __restrict__ x,
                                                          float* __restrict__ y) {
    __shared__ float sm[NQ];  // 16 KB
    const int t = threadIdx.x;
    const size_t base = (size_t)blockIdx.x * NQ;
    const float scale = 0.015625f;  // HAD_SCALE / X_H_SCALE = 1/sqrt(4096)
    float v[16];

    // ---- P1: v[r] = x[r*256 + t] ----
    const float* xr = x + base + t;
#pragma unroll
    for (int r = 0; r < 16; r++)
        v[r] = xr[r * 256] * scale;
    butterfly16(v);  // dims 8-11

    // Pattern A: conflict-free STS
#pragma unroll
    for (int r = 0; r < 16; r++)
        sm[s_idx(r * 256 + t)] = v[r];
    __syncthreads();

    // ---- P2: regs = dims 0-3 (pattern B, float4, in-place) ----
#pragma unroll
    for (int q = 0; q < 4; q++) {
        float4 f = *reinterpret_cast<const float4*>(sm + s_idx((t << 4) | (q << 2)));
        v[4 * q + 0] = f.x;
        v[4 * q + 1] = f.y;
        v[4 * q + 2] = f.z;
        v[4 * q + 3] = f.w;
    }
    butterfly16(v);  // dims 0-3
#pragma unroll
    for (int q = 0; q < 4; q++) {
        *reinterpret_cast<float4*>(sm + s_idx((t << 4) | (q << 2))) =
            make_float4(v[4 * q], v[4 * q + 1], v[4 * q + 2], v[4 * q + 3]);
    }
    __syncthreads();

    // ---- P3: regs = dims 4-7 (pattern C) ----
    const int ebase = (t & 15) | ((t >> 4) << 8);
#pragma unroll
    for (int i = 0; i < 16; i++)
        v[i] = sm[s_idx(ebase | (i << 4))];
    butterfly16(v);  // dims 4-7

    // ---- Store: 16 x STG.32; each instruction covers two full 64B segments ----
    float* yr = y + base;
#pragma unroll
    for (int i = 0; i < 16; i++)
        yr[ebase | (i << 4)] = v[i];
}

extern "C" void kernel_launch(void* const* d_in, const int* in_sizes, int n_in,
                              void* d_out, int out_size) {
    const float* x = (const float*)d_in[0];
    float* y = (float*)d_out;
    const int rows = in_sizes[0] / NQ;  // 8192 rows of 4096
    fwht4096_kernel<<<rows, TPB>>>(x, y);
}